// round 8
// baseline (speedup 1.0000x reference)
#include <cuda_runtime.h>
#include <cuda_bf16.h>
#include <math.h>

#define BATCH 2
#define SEQ 4096
#define R (BATCH*SEQ)          // 8192 rows
#define DM 384                 // d_model
#define DI 768                 // d_inner
#define DS 16                  // d_state
#define DTR 24                 // dt_rank
#define XPN (DTR + 2*DS)       // 56
#define DFF 1536               // 4*d_model
#define LN_EPS 1e-5f

// ---------------- scratch (static device globals; no allocs) ----------------
__device__ float g_u   [R*DM];
__device__ float g_xz  [R*2*DI];
__device__ float g_xc  [R*DI];
__device__ float g_xdbl[R*XPN];
__device__ float g_dt  [R*DI];
__device__ float g_y   [R*DI];
__device__ float g_x1  [R*DM];
__device__ float g_u2  [R*DM];
__device__ float g_hf  [R*DFF];

// ---------------- LayerNorm ----------------
__global__ void ln_kernel(const float* __restrict__ x,
                          const float* __restrict__ w,
                          const float* __restrict__ b,
                          float* __restrict__ out) {
    int row = blockIdx.x;
    const float* xr = x + row*DM;
    int tid = threadIdx.x;
    float s = 0.f, ss = 0.f;
    for (int i = tid; i < DM; i += blockDim.x) {
        float v = xr[i];
        s += v; ss += v*v;
    }
    for (int o = 16; o > 0; o >>= 1) {
        s  += __shfl_xor_sync(0xffffffffu, s, o);
        ss += __shfl_xor_sync(0xffffffffu, ss, o);
    }
    __shared__ float sh_s[4], sh_ss[4];
    int wid = tid >> 5, lid = tid & 31;
    if (lid == 0) { sh_s[wid] = s; sh_ss[wid] = ss; }
    __syncthreads();
    if (wid == 0) {
        s  = (lid < (blockDim.x>>5)) ? sh_s[lid]  : 0.f;
        ss = (lid < (blockDim.x>>5)) ? sh_ss[lid] : 0.f;
        for (int o = 2; o > 0; o >>= 1) {
            s  += __shfl_xor_sync(0xffffffffu, s, o);
            ss += __shfl_xor_sync(0xffffffffu, ss, o);
        }
        if (lid == 0) { sh_s[0] = s; sh_ss[0] = ss; }
    }
    __syncthreads();
    float mu  = sh_s[0] / DM;
    float var = sh_ss[0] / DM - mu*mu;
    float inv = rsqrtf(var + LN_EPS);
    for (int i = tid; i < DM; i += blockDim.x)
        out[row*DM + i] = (xr[i] - mu) * inv * w[i] + b[i];
}

// ================= TF32 GEMM: deep cp.async pipeline + ldmatrix =============
// C[m,n] = sum_k A[m,k] * W[n,k]  (+bias, act, +residual)
// Warp layout: 2 warps (M) x 4 warps (N), 256 threads.
// Block tile = (2*MF*16) x (4*NF*8). Smem [row][k], row stride SA=20 floats.
// STG-stage circular cp.async pipeline in dynamic smem.

#define SA 20

__device__ __forceinline__ void mma_tf32(float* c, const unsigned* a, const unsigned* b) {
    asm volatile(
        "mma.sync.aligned.m16n8k8.row.col.f32.tf32.tf32.f32 "
        "{%0,%1,%2,%3}, {%4,%5,%6,%7}, {%8,%9}, {%0,%1,%2,%3};"
        : "+f"(c[0]), "+f"(c[1]), "+f"(c[2]), "+f"(c[3])
        : "r"(a[0]), "r"(a[1]), "r"(a[2]), "r"(a[3]), "r"(b[0]), "r"(b[1]));
}

__device__ __forceinline__ void ldsm_x4(unsigned* r, unsigned addr) {
    asm volatile("ldmatrix.sync.aligned.m8n8.x4.shared.b16 {%0,%1,%2,%3}, [%4];"
        : "=r"(r[0]), "=r"(r[1]), "=r"(r[2]), "=r"(r[3]) : "r"(addr));
}
__device__ __forceinline__ void ldsm_x2(unsigned* r, unsigned addr) {
    asm volatile("ldmatrix.sync.aligned.m8n8.x2.shared.b16 {%0,%1}, [%2];"
        : "=r"(r[0]), "=r"(r[1]) : "r"(addr));
}

__device__ __forceinline__ void cp_async16(unsigned dst, const void* src, int src_bytes) {
    asm volatile("cp.async.cg.shared.global [%0], [%1], 16, %2;"
        :: "r"(dst), "l"(src), "r"(src_bytes));
}
__device__ __forceinline__ void cp_commit() {
    asm volatile("cp.async.commit_group;");
}
template<int N_>
__device__ __forceinline__ void cp_wait() {
    asm volatile("cp.async.wait_group %0;" :: "n"(N_));
}

template<int MF, int NF, int STG>
__global__ void __launch_bounds__(256, 2)
gemm_tf32(const float* __restrict__ A, int lda,
          const float* __restrict__ W,
          float* __restrict__ C, int ldc,
          int N, int K,
          const float* __restrict__ bias,
          const float* __restrict__ residual, int ldr,
          int act) {
    constexpr int BM = 2*MF*16;
    constexpr int BN = 4*NF*8;
    constexpr int AR = BM/64;
    constexpr int BR = BN/64;

    extern __shared__ __align__(16) unsigned smem_dyn[];
    unsigned* As = smem_dyn;                  // STG*BM*SA
    unsigned* Bs = smem_dyn + STG*BM*SA;      // STG*BN*SA

    const int bm = blockIdx.y * BM;
    const int bn = blockIdx.x * BN;
    const int tid = threadIdx.x;
    const int wid = tid >> 5;
    const int lane = tid & 31;
    const int g   = lane >> 2;
    const int tig = lane & 3;
    const int warp_m = wid & 1;
    const int warp_n = wid >> 1;

    const int lrow = tid >> 2;        // 0..63
    const int lkq  = (tid & 3) * 4;   // 0,4,8,12

    const int a_lane_off = ((lane & 7) + ((lane >> 3) & 1) * 8) * SA
                         + ((lane >> 4) & 1) * 4;
    const int b_lane_off = (lane & 7) * SA + ((lane >> 3) & 1) * 4;

    unsigned as_base, bs_base;
    {
        unsigned long long t;
        t = __cvta_generic_to_shared(As); as_base = (unsigned)t;
        t = __cvta_generic_to_shared(Bs); bs_base = (unsigned)t;
    }

    float acc[MF][NF][4];
    #pragma unroll
    for (int i = 0; i < MF; i++)
        #pragma unroll
        for (int j = 0; j < NF; j++)
            #pragma unroll
            for (int q = 0; q < 4; q++) acc[i][j][q] = 0.f;

    const int nk = (K + 15) / 16;

    auto issueTile = [&](int st, int t) {
        const int k0 = t * 16;
        const int kb = (k0 + lkq <= K - 4) ? 16 : 0;
        #pragma unroll
        for (int r = 0; r < AR; r++) {
            const float* src = A + (size_t)(bm + lrow + r*64)*lda + k0 + lkq;
            unsigned dst = as_base + 4u*((unsigned)(st*BM + lrow + r*64)*SA + lkq);
            cp_async16(dst, src, kb);
        }
        #pragma unroll
        for (int r = 0; r < BR; r++) {
            int gn = bn + lrow + r*64;
            int bb = (gn < N) ? kb : 0;
            int gns = (gn < N) ? gn : (N - 1);
            const float* src = W + (size_t)gns*K + k0 + lkq;
            unsigned dst = bs_base + 4u*((unsigned)(st*BN + lrow + r*64)*SA + lkq);
            cp_async16(dst, src, bb);
        }
    };

    // prologue: fill stages 0..STG-2
    #pragma unroll
    for (int s = 0; s < STG-1; s++) {
        if (s < nk) issueTile(s, s);
        cp_commit();
    }
    cp_wait<STG-2>();
    __syncthreads();

    int stage = 0;
    for (int t = 0; t < nk; t++) {
        {
            int tn = t + STG - 1;
            if (tn < nk) issueTile(tn % STG, tn);
            cp_commit();
        }

        const unsigned a_buf = as_base + 4u*((unsigned)(stage*BM)*SA);
        const unsigned b_buf = bs_base + 4u*((unsigned)(stage*BN)*SA);

        #pragma unroll
        for (int s = 0; s < 2; s++) {
            const int ks = s * 8;
            unsigned af[MF][4], bf[NF][2];
            #pragma unroll
            for (int i = 0; i < MF; i++) {
                unsigned addr = a_buf
                    + 4u*((unsigned)((warp_m*MF + i)*16)*SA + ks + a_lane_off);
                ldsm_x4(af[i], addr);
            }
            #pragma unroll
            for (int j = 0; j < NF; j++) {
                unsigned addr = b_buf
                    + 4u*((unsigned)(warp_n*(NF*8) + j*8)*SA + ks + b_lane_off);
                ldsm_x2(bf[j], addr);
            }
            #pragma unroll
            for (int i = 0; i < MF; i++)
                #pragma unroll
                for (int j = 0; j < NF; j++)
                    mma_tf32(acc[i][j], af[i], bf[j]);
        }

        cp_wait<STG-2>();
        __syncthreads();
        stage = (stage + 1 < STG) ? stage + 1 : 0;
    }

    // ---- epilogue ----
    #pragma unroll
    for (int i = 0; i < MF; i++) {
        #pragma unroll
        for (int j = 0; j < NF; j++) {
            int nc = bn + warp_n*(NF*8) + j*8 + 2*tig;
            #pragma unroll
            for (int half = 0; half < 2; half++) {
                int gm = bm + warp_m*(MF*16) + i*16 + g + half*8;
                #pragma unroll
                for (int e = 0; e < 2; e++) {
                    int gn = nc + e;
                    if (gn < N) {
                        float v = acc[i][j][half*2 + e];
                        if (bias) v += bias[gn];
                        if (act == 1) v = (v > 20.f) ? v : log1pf(expf(v));
                        else if (act == 2) v = fmaxf(v, 0.f);
                        if (residual) v += residual[(size_t)gm*ldr + gn];
                        C[(size_t)gm*ldc + gn] = v;
                    }
                }
            }
        }
    }
}

// ---------------- depthwise causal conv (k=4) + SiLU ----------------
__global__ void conv_kernel(const float* __restrict__ xz,
                            const float* __restrict__ cw,
                            const float* __restrict__ cb,
                            float* __restrict__ xc) {
    int idx = blockIdx.x * blockDim.x + threadIdx.x;
    if (idx >= R*DI) return;
    int d = idx % DI;
    int row = idx / DI;
    int s = row % SEQ;
    float acc = cb[d];
    #pragma unroll
    for (int j = 0; j < 4; j++) {
        int sp = s - 3 + j;
        if (sp >= 0)
            acc += xz[(size_t)(row - 3 + j)*(2*DI) + d] * cw[d*4 + j];
    }
    xc[idx] = acc / (1.f + expf(-acc));
}

// ---------------- selective scan (+ fused gate) -----------------------------
__global__ void scan_kernel(const float* __restrict__ dt,
                            const float* __restrict__ xc,
                            const float* __restrict__ xdbl,
                            const float* __restrict__ A_log,
                            const float* __restrict__ Dv,
                            const float* __restrict__ xz,
                            float* __restrict__ y) {
    int g = (blockIdx.x * blockDim.x + threadIdx.x) >> 4;
    int n = threadIdx.x & 15;
    if (g >= BATCH*DI) return;
    int b = g / DI, d = g % DI;
    int bS = b * SEQ;
    float Aa = -expf(A_log[d*DS + n]);
    float Dd = Dv[d];
    float h = 0.f;

    const int U = 8;
    for (int s0 = 0; s0 < SEQ; s0 += U) {
        float dtv[U], xv[U], Bv[U], Cv[U], zv[U], dA[U], p[U];
        #pragma unroll
        for (int u = 0; u < U; u++) {
            int row = bS + s0 + u;
            dtv[u] = dt[(size_t)row*DI + d];
            xv[u]  = xc[(size_t)row*DI + d];
            Bv[u]  = xdbl[(size_t)row*XPN + DTR + n];
            Cv[u]  = xdbl[(size_t)row*XPN + DTR + DS + n];
            zv[u]  = xz[(size_t)row*(2*DI) + DI + d];
            dA[u]  = expf(dtv[u] * Aa);
        }
        #pragma unroll
        for (int u = 0; u < U; u++) {
            h = fmaf(dA[u], h, dtv[u]*Bv[u]*xv[u]);
            p[u] = h * Cv[u];
        }
        #pragma unroll
        for (int o = 1; o < 16; o <<= 1) {
            #pragma unroll
            for (int u = 0; u < U; u++)
                p[u] += __shfl_xor_sync(0xffffffffu, p[u], o);
        }
        if (n == 0) {
            #pragma unroll
            for (int u = 0; u < U; u++) {
                float z = zv[u];
                float sz = z / (1.f + expf(-z));
                y[(size_t)(bS + s0 + u)*DI + d] = (p[u] + xv[u]*Dd) * sz;
            }
        }
    }
}

// ---------------- launch ----------------
extern "C" void kernel_launch(void* const* d_in, const int* in_sizes, int n_in,
                              void* d_out, int out_size) {
    const float* x         = (const float*)d_in[0];
    const float* in_proj_w = (const float*)d_in[1];
    const float* conv_w    = (const float*)d_in[2];
    const float* conv_b    = (const float*)d_in[3];
    const float* x_proj_w  = (const float*)d_in[4];
    const float* dt_proj_w = (const float*)d_in[5];
    const float* dt_proj_b = (const float*)d_in[6];
    const float* A_log     = (const float*)d_in[7];
    const float* Dp        = (const float*)d_in[8];
    const float* out_proj_w= (const float*)d_in[9];
    const float* ln1_w     = (const float*)d_in[10];
    const float* ln1_b     = (const float*)d_in[11];
    const float* ln2_w     = (const float*)d_in[12];
    const float* ln2_b     = (const float*)d_in[13];
    const float* ffn_w1    = (const float*)d_in[14];
    const float* ffn_b1    = (const float*)d_in[15];
    const float* ffn_w2    = (const float*)d_in[16];
    const float* ffn_b2    = (const float*)d_in[17];
    float* out = (float*)d_out;

    float *u, *xz, *xc, *xdbl, *dt, *y, *x1, *u2, *hf;
    cudaGetSymbolAddress((void**)&u,    g_u);
    cudaGetSymbolAddress((void**)&xz,   g_xz);
    cudaGetSymbolAddress((void**)&xc,   g_xc);
    cudaGetSymbolAddress((void**)&xdbl, g_xdbl);
    cudaGetSymbolAddress((void**)&dt,   g_dt);
    cudaGetSymbolAddress((void**)&y,    g_y);
    cudaGetSymbolAddress((void**)&x1,   g_x1);
    cudaGetSymbolAddress((void**)&u2,   g_u2);
    cudaGetSymbolAddress((void**)&hf,   g_hf);

    // smem sizes
    const int SM_BIG   = 5*(128+64)*SA*4;   // <4,2,5>: 76800 B
    const int SM_SMALL = 4*(64+64)*SA*4;    // <2,2,4>: 40960 B
    cudaFuncSetAttribute((const void*)gemm_tf32<4,2,5>,
                         cudaFuncAttributeMaxDynamicSharedMemorySize, SM_BIG);

    // 1. LN1
    ln_kernel<<<R, 128>>>(x, ln1_w, ln1_b, u);

    // 2. in_proj (N=1536,K=384): 128x64 tiles, 5 stages
    gemm_tf32<4,2,5><<<dim3((2*DI+63)/64, R/128), 256, SM_BIG>>>(
        u, DM, in_proj_w, xz, 2*DI, 2*DI, DM, nullptr, nullptr, 0, 0);

    // 3. conv + silu
    conv_kernel<<<(R*DI + 255)/256, 256>>>(xz, conv_w, conv_b, xc);

    // 4. x_proj (N=56,K=768): 64x64, 4 stages
    gemm_tf32<2,2,4><<<dim3((XPN+63)/64, R/64), 256, SM_SMALL>>>(
        xc, DI, x_proj_w, xdbl, XPN, XPN, DI, nullptr, nullptr, 0, 0);

    // 5. dt_proj + softplus (N=768,K=24): 64x64, 4 stages
    gemm_tf32<2,2,4><<<dim3((DI+63)/64, R/64), 256, SM_SMALL>>>(
        xdbl, XPN, dt_proj_w, dt, DI, DI, DTR, dt_proj_b, nullptr, 0, 1);

    // 6. selective scan + gate
    {
        int total = BATCH*DI*16;
        scan_kernel<<<(total + 127)/128, 128>>>(dt, xc, xdbl, A_log, Dp, xz, y);
    }

    // 7. out_proj + residual (N=384,K=768): 128x64, 5 stages
    gemm_tf32<4,2,5><<<dim3((DM+63)/64, R/128), 256, SM_BIG>>>(
        y, DI, out_proj_w, x1, DM, DM, DI, nullptr, x, DM, 0);

    // 8. LN2
    ln_kernel<<<R, 128>>>(x1, ln2_w, ln2_b, u2);

    // 9. ffn1 + relu (N=1536,K=384): 128x64, 5 stages
    gemm_tf32<4,2,5><<<dim3((DFF+63)/64, R/128), 256, SM_BIG>>>(
        u2, DM, ffn_w1, hf, DFF, DFF, DM, ffn_b1, nullptr, 0, 2);

    // 10. ffn2 + bias + residual (N=384,K=1536): 128x64, 5 stages
    gemm_tf32<4,2,5><<<dim3((DM+63)/64, R/128), 256, SM_BIG>>>(
        hf, DFF, ffn_w2, out, DM, DM, DFF, ffn_b2, x1, DM, 0);
}

// round 9
// speedup vs baseline: 1.7437x; 1.7437x over previous
#include <cuda_runtime.h>
#include <cuda_bf16.h>
#include <math.h>

#define BATCH 2
#define SEQ 4096
#define R (BATCH*SEQ)          // 8192 rows
#define DM 384                 // d_model
#define DI 768                 // d_inner
#define DS 16                  // d_state
#define DTR 24                 // dt_rank
#define XPN (DTR + 2*DS)       // 56
#define DFF 1536               // 4*d_model
#define LN_EPS 1e-5f
#define CHL 128                // chunk length for scan
#define NCH (SEQ/CHL)          // 32 chunks

// ---------------- scratch (static device globals; no allocs) ----------------
__device__ float g_u   [R*DM];
__device__ float g_xz  [R*2*DI];
__device__ float g_xc  [R*DI];
__device__ float g_xdbl[R*XPN];
__device__ float g_dt  [R*DI];
__device__ float g_y   [R*DI];
__device__ float g_x1  [R*DM];
__device__ float g_u2  [R*DM];
__device__ float g_hf  [R*DFF];
__device__ float g_P   [BATCH*NCH*DI*DS];   // chunk transition products
__device__ float g_E   [BATCH*NCH*DI*DS];   // chunk end states (zero init)
__device__ float g_H   [BATCH*NCH*DI*DS];   // chunk entry states

// ---------------- LayerNorm ----------------
__global__ void ln_kernel(const float* __restrict__ x,
                          const float* __restrict__ w,
                          const float* __restrict__ b,
                          float* __restrict__ out) {
    int row = blockIdx.x;
    const float* xr = x + row*DM;
    int tid = threadIdx.x;
    float s = 0.f, ss = 0.f;
    for (int i = tid; i < DM; i += blockDim.x) {
        float v = xr[i];
        s += v; ss += v*v;
    }
    for (int o = 16; o > 0; o >>= 1) {
        s  += __shfl_xor_sync(0xffffffffu, s, o);
        ss += __shfl_xor_sync(0xffffffffu, ss, o);
    }
    __shared__ float sh_s[4], sh_ss[4];
    int wid = tid >> 5, lid = tid & 31;
    if (lid == 0) { sh_s[wid] = s; sh_ss[wid] = ss; }
    __syncthreads();
    if (wid == 0) {
        s  = (lid < (blockDim.x>>5)) ? sh_s[lid]  : 0.f;
        ss = (lid < (blockDim.x>>5)) ? sh_ss[lid] : 0.f;
        for (int o = 2; o > 0; o >>= 1) {
            s  += __shfl_xor_sync(0xffffffffu, s, o);
            ss += __shfl_xor_sync(0xffffffffu, ss, o);
        }
        if (lid == 0) { sh_s[0] = s; sh_ss[0] = ss; }
    }
    __syncthreads();
    float mu  = sh_s[0] / DM;
    float var = sh_ss[0] / DM - mu*mu;
    float inv = rsqrtf(var + LN_EPS);
    for (int i = tid; i < DM; i += blockDim.x)
        out[row*DM + i] = (xr[i] - mu) * inv * w[i] + b[i];
}

// ================= TF32 GEMM: cp.async pipeline + ldmatrix ==================
#define SA 20

__device__ __forceinline__ void mma_tf32(float* c, const unsigned* a, const unsigned* b) {
    asm volatile(
        "mma.sync.aligned.m16n8k8.row.col.f32.tf32.tf32.f32 "
        "{%0,%1,%2,%3}, {%4,%5,%6,%7}, {%8,%9}, {%0,%1,%2,%3};"
        : "+f"(c[0]), "+f"(c[1]), "+f"(c[2]), "+f"(c[3])
        : "r"(a[0]), "r"(a[1]), "r"(a[2]), "r"(a[3]), "r"(b[0]), "r"(b[1]));
}

__device__ __forceinline__ void ldsm_x4(unsigned* r, unsigned addr) {
    asm volatile("ldmatrix.sync.aligned.m8n8.x4.shared.b16 {%0,%1,%2,%3}, [%4];"
        : "=r"(r[0]), "=r"(r[1]), "=r"(r[2]), "=r"(r[3]) : "r"(addr));
}
__device__ __forceinline__ void ldsm_x2(unsigned* r, unsigned addr) {
    asm volatile("ldmatrix.sync.aligned.m8n8.x2.shared.b16 {%0,%1}, [%2];"
        : "=r"(r[0]), "=r"(r[1]) : "r"(addr));
}

__device__ __forceinline__ void cp_async16(unsigned dst, const void* src, int src_bytes) {
    asm volatile("cp.async.cg.shared.global [%0], [%1], 16, %2;"
        :: "r"(dst), "l"(src), "r"(src_bytes));
}
__device__ __forceinline__ void cp_commit() {
    asm volatile("cp.async.commit_group;");
}
template<int N_>
__device__ __forceinline__ void cp_wait() {
    asm volatile("cp.async.wait_group %0;" :: "n"(N_));
}

template<int MF, int NF, int STG>
__global__ void __launch_bounds__(256, 2)
gemm_tf32(const float* __restrict__ A, int lda,
          const float* __restrict__ W,
          float* __restrict__ C, int ldc,
          int N, int K,
          const float* __restrict__ bias,
          const float* __restrict__ residual, int ldr,
          int act) {
    constexpr int BM = 2*MF*16;
    constexpr int BN = 4*NF*8;
    constexpr int AR = BM/64;
    constexpr int BR = BN/64;

    extern __shared__ __align__(16) unsigned smem_dyn[];
    unsigned* As = smem_dyn;
    unsigned* Bs = smem_dyn + STG*BM*SA;

    const int bm = blockIdx.y * BM;
    const int bn = blockIdx.x * BN;
    const int tid = threadIdx.x;
    const int wid = tid >> 5;
    const int lane = tid & 31;
    const int g   = lane >> 2;
    const int tig = lane & 3;
    const int warp_m = wid & 1;
    const int warp_n = wid >> 1;

    const int lrow = tid >> 2;
    const int lkq  = (tid & 3) * 4;

    const int a_lane_off = ((lane & 7) + ((lane >> 3) & 1) * 8) * SA
                         + ((lane >> 4) & 1) * 4;
    const int b_lane_off = (lane & 7) * SA + ((lane >> 3) & 1) * 4;

    unsigned as_base, bs_base;
    {
        unsigned long long t;
        t = __cvta_generic_to_shared(As); as_base = (unsigned)t;
        t = __cvta_generic_to_shared(Bs); bs_base = (unsigned)t;
    }

    float acc[MF][NF][4];
    #pragma unroll
    for (int i = 0; i < MF; i++)
        #pragma unroll
        for (int j = 0; j < NF; j++)
            #pragma unroll
            for (int q = 0; q < 4; q++) acc[i][j][q] = 0.f;

    const int nk = (K + 15) / 16;

    auto issueTile = [&](int st, int t) {
        const int k0 = t * 16;
        const int kb = (k0 + lkq <= K - 4) ? 16 : 0;
        #pragma unroll
        for (int r = 0; r < AR; r++) {
            const float* src = A + (size_t)(bm + lrow + r*64)*lda + k0 + lkq;
            unsigned dst = as_base + 4u*((unsigned)(st*BM + lrow + r*64)*SA + lkq);
            cp_async16(dst, src, kb);
        }
        #pragma unroll
        for (int r = 0; r < BR; r++) {
            int gn = bn + lrow + r*64;
            int bb = (gn < N) ? kb : 0;
            int gns = (gn < N) ? gn : (N - 1);
            const float* src = W + (size_t)gns*K + k0 + lkq;
            unsigned dst = bs_base + 4u*((unsigned)(st*BN + lrow + r*64)*SA + lkq);
            cp_async16(dst, src, bb);
        }
    };

    #pragma unroll
    for (int s = 0; s < STG-1; s++) {
        if (s < nk) issueTile(s, s);
        cp_commit();
    }
    cp_wait<STG-2>();
    __syncthreads();

    int stage = 0;
    for (int t = 0; t < nk; t++) {
        {
            int tn = t + STG - 1;
            if (tn < nk) issueTile(tn % STG, tn);
            cp_commit();
        }

        const unsigned a_buf = as_base + 4u*((unsigned)(stage*BM)*SA);
        const unsigned b_buf = bs_base + 4u*((unsigned)(stage*BN)*SA);

        #pragma unroll
        for (int s = 0; s < 2; s++) {
            const int ks = s * 8;
            unsigned af[MF][4], bf[NF][2];
            #pragma unroll
            for (int i = 0; i < MF; i++) {
                unsigned addr = a_buf
                    + 4u*((unsigned)((warp_m*MF + i)*16)*SA + ks + a_lane_off);
                ldsm_x4(af[i], addr);
            }
            #pragma unroll
            for (int j = 0; j < NF; j++) {
                unsigned addr = b_buf
                    + 4u*((unsigned)(warp_n*(NF*8) + j*8)*SA + ks + b_lane_off);
                ldsm_x2(bf[j], addr);
            }
            #pragma unroll
            for (int i = 0; i < MF; i++)
                #pragma unroll
                for (int j = 0; j < NF; j++)
                    mma_tf32(acc[i][j], af[i], bf[j]);
        }

        cp_wait<STG-2>();
        __syncthreads();
        stage = (stage + 1 < STG) ? stage + 1 : 0;
    }

    #pragma unroll
    for (int i = 0; i < MF; i++) {
        #pragma unroll
        for (int j = 0; j < NF; j++) {
            int nc = bn + warp_n*(NF*8) + j*8 + 2*tig;
            #pragma unroll
            for (int half = 0; half < 2; half++) {
                int gm = bm + warp_m*(MF*16) + i*16 + g + half*8;
                #pragma unroll
                for (int e = 0; e < 2; e++) {
                    int gn = nc + e;
                    if (gn < N) {
                        float v = acc[i][j][half*2 + e];
                        if (bias) v += bias[gn];
                        if (act == 1) v = (v > 20.f) ? v : log1pf(expf(v));
                        else if (act == 2) v = fmaxf(v, 0.f);
                        if (residual) v += residual[(size_t)gm*ldr + gn];
                        C[(size_t)gm*ldc + gn] = v;
                    }
                }
            }
        }
    }
}

// ---------------- depthwise causal conv (k=4) + SiLU ----------------
__global__ void conv_kernel(const float* __restrict__ xz,
                            const float* __restrict__ cw,
                            const float* __restrict__ cb,
                            float* __restrict__ xc) {
    int idx = blockIdx.x * blockDim.x + threadIdx.x;
    if (idx >= R*DI) return;
    int d = idx % DI;
    int row = idx / DI;
    int s = row % SEQ;
    float acc = cb[d];
    #pragma unroll
    for (int j = 0; j < 4; j++) {
        int sp = s - 3 + j;
        if (sp >= 0)
            acc += xz[(size_t)(row - 3 + j)*(2*DI) + d] * cw[d*4 + j];
    }
    xc[idx] = acc / (1.f + expf(-acc));
}

// =============== chunked selective scan: 3 passes ===========================
// Recurrence h_t = dA_t h_{t-1} + dt_t B_t x_t ; y_t = <h_t, C_t>.
// Chunked: P_c = prod dA over chunk, E_c = end state with h0=0,
// H_{c+1} = P_c H_c + E_c, then re-scan chunks from true H_c.
// Thread layout (passes A/C): gid = ((b*NCH + c)*DI + d)*16 + n.

__global__ void scanA_kernel(const float* __restrict__ dt,
                             const float* __restrict__ xc,
                             const float* __restrict__ xdbl,
                             const float* __restrict__ A_log,
                             float* __restrict__ P,
                             float* __restrict__ E) {
    int gid = blockIdx.x * blockDim.x + threadIdx.x;
    if (gid >= BATCH*NCH*DI*DS) return;
    int n  = gid & 15;
    int g2 = gid >> 4;
    int d  = g2 % DI;
    int bc = g2 / DI;            // b*NCH + c
    int c  = bc % NCH;
    int b  = bc / NCH;
    int row0 = b*SEQ + c*CHL;

    float Aa = -expf(A_log[d*DS + n]);
    float h = 0.f, p = 1.f;

    const int U = 8;
    for (int s0 = 0; s0 < CHL; s0 += U) {
        float dtv[U], xv[U], Bv[U], dA[U];
        #pragma unroll
        for (int u = 0; u < U; u++) {
            int row = row0 + s0 + u;
            dtv[u] = dt[(size_t)row*DI + d];
            xv[u]  = xc[(size_t)row*DI + d];
            Bv[u]  = xdbl[(size_t)row*XPN + DTR + n];
        }
        #pragma unroll
        for (int u = 0; u < U; u++) dA[u] = expf(dtv[u] * Aa);
        #pragma unroll
        for (int u = 0; u < U; u++) {
            h = fmaf(dA[u], h, dtv[u]*Bv[u]*xv[u]);
            p *= dA[u];
        }
    }
    P[gid] = p;
    E[gid] = h;
}

__global__ void scanB_kernel(const float* __restrict__ P,
                             const float* __restrict__ E,
                             float* __restrict__ H) {
    int t = blockIdx.x * blockDim.x + threadIdx.x;
    if (t >= BATCH*DI*DS) return;
    int n  = t & 15;
    int d  = (t >> 4) % DI;
    int b  = t / (DI*DS);
    float h = 0.f;
    for (int c = 0; c < NCH; c++) {
        size_t idx = ((size_t)(b*NCH + c)*DI + d)*DS + n;
        H[idx] = h;
        h = fmaf(P[idx], h, E[idx]);
    }
}

__global__ void scanC_kernel(const float* __restrict__ dt,
                             const float* __restrict__ xc,
                             const float* __restrict__ xdbl,
                             const float* __restrict__ A_log,
                             const float* __restrict__ Dv,
                             const float* __restrict__ xz,
                             const float* __restrict__ H,
                             float* __restrict__ y) {
    int gid = blockIdx.x * blockDim.x + threadIdx.x;
    if (gid >= BATCH*NCH*DI*DS) return;
    int n  = gid & 15;
    int g2 = gid >> 4;
    int d  = g2 % DI;
    int bc = g2 / DI;
    int c  = bc % NCH;
    int b  = bc / NCH;
    int row0 = b*SEQ + c*CHL;

    float Aa = -expf(A_log[d*DS + n]);
    float Dd = Dv[d];
    float h  = H[gid];

    const int U = 8;
    for (int s0 = 0; s0 < CHL; s0 += U) {
        float dtv[U], xv[U], Bv[U], Cv[U], zv[U], dA[U], p[U];
        #pragma unroll
        for (int u = 0; u < U; u++) {
            int row = row0 + s0 + u;
            dtv[u] = dt[(size_t)row*DI + d];
            xv[u]  = xc[(size_t)row*DI + d];
            Bv[u]  = xdbl[(size_t)row*XPN + DTR + n];
            Cv[u]  = xdbl[(size_t)row*XPN + DTR + DS + n];
            zv[u]  = xz[(size_t)row*(2*DI) + DI + d];
        }
        #pragma unroll
        for (int u = 0; u < U; u++) dA[u] = expf(dtv[u] * Aa);
        #pragma unroll
        for (int u = 0; u < U; u++) {
            h = fmaf(dA[u], h, dtv[u]*Bv[u]*xv[u]);
            p[u] = h * Cv[u];
        }
        #pragma unroll
        for (int o = 1; o < 16; o <<= 1) {
            #pragma unroll
            for (int u = 0; u < U; u++)
                p[u] += __shfl_xor_sync(0xffffffffu, p[u], o);
        }
        if (n == 0) {
            #pragma unroll
            for (int u = 0; u < U; u++) {
                float z = zv[u];
                float sz = z / (1.f + expf(-z));
                y[(size_t)(row0 + s0 + u)*DI + d] = (p[u] + xv[u]*Dd) * sz;
            }
        }
    }
}

// ---------------- launch ----------------
extern "C" void kernel_launch(void* const* d_in, const int* in_sizes, int n_in,
                              void* d_out, int out_size) {
    const float* x         = (const float*)d_in[0];
    const float* in_proj_w = (const float*)d_in[1];
    const float* conv_w    = (const float*)d_in[2];
    const float* conv_b    = (const float*)d_in[3];
    const float* x_proj_w  = (const float*)d_in[4];
    const float* dt_proj_w = (const float*)d_in[5];
    const float* dt_proj_b = (const float*)d_in[6];
    const float* A_log     = (const float*)d_in[7];
    const float* Dp        = (const float*)d_in[8];
    const float* out_proj_w= (const float*)d_in[9];
    const float* ln1_w     = (const float*)d_in[10];
    const float* ln1_b     = (const float*)d_in[11];
    const float* ln2_w     = (const float*)d_in[12];
    const float* ln2_b     = (const float*)d_in[13];
    const float* ffn_w1    = (const float*)d_in[14];
    const float* ffn_b1    = (const float*)d_in[15];
    const float* ffn_w2    = (const float*)d_in[16];
    const float* ffn_b2    = (const float*)d_in[17];
    float* out = (float*)d_out;

    float *u, *xz, *xc, *xdbl, *dt, *y, *x1, *u2, *hf, *Pp, *Ep, *Hp;
    cudaGetSymbolAddress((void**)&u,    g_u);
    cudaGetSymbolAddress((void**)&xz,   g_xz);
    cudaGetSymbolAddress((void**)&xc,   g_xc);
    cudaGetSymbolAddress((void**)&xdbl, g_xdbl);
    cudaGetSymbolAddress((void**)&dt,   g_dt);
    cudaGetSymbolAddress((void**)&y,    g_y);
    cudaGetSymbolAddress((void**)&x1,   g_x1);
    cudaGetSymbolAddress((void**)&u2,   g_u2);
    cudaGetSymbolAddress((void**)&hf,   g_hf);
    cudaGetSymbolAddress((void**)&Pp,   g_P);
    cudaGetSymbolAddress((void**)&Ep,   g_E);
    cudaGetSymbolAddress((void**)&Hp,   g_H);

    const int SM_BIG   = 3*(128+64)*SA*4;   // <4,2,3>: 46080 B
    const int SM_SMALL = 4*(64+64)*SA*4;    // <2,2,4>: 40960 B

    // 1. LN1
    ln_kernel<<<R, 128>>>(x, ln1_w, ln1_b, u);

    // 2. in_proj (N=1536,K=384): 128x64, 3 stages
    gemm_tf32<4,2,3><<<dim3((2*DI+63)/64, R/128), 256, SM_BIG>>>(
        u, DM, in_proj_w, xz, 2*DI, 2*DI, DM, nullptr, nullptr, 0, 0);

    // 3. conv + silu
    conv_kernel<<<(R*DI + 255)/256, 256>>>(xz, conv_w, conv_b, xc);

    // 4. x_proj (N=56,K=768): 64x64, 4 stages
    gemm_tf32<2,2,4><<<dim3((XPN+63)/64, R/64), 256, SM_SMALL>>>(
        xc, DI, x_proj_w, xdbl, XPN, XPN, DI, nullptr, nullptr, 0, 0);

    // 5. dt_proj + softplus (N=768,K=24): 64x64, 4 stages
    gemm_tf32<2,2,4><<<dim3((DI+63)/64, R/64), 256, SM_SMALL>>>(
        xdbl, XPN, dt_proj_w, dt, DI, DI, DTR, dt_proj_b, nullptr, 0, 1);

    // 6. chunked selective scan (3 passes) + fused gate
    {
        int totA = BATCH*NCH*DI*DS;          // 786432
        scanA_kernel<<<(totA + 127)/128, 128>>>(dt, xc, xdbl, A_log, Pp, Ep);
        int totB = BATCH*DI*DS;              // 24576
        scanB_kernel<<<(totB + 127)/128, 128>>>(Pp, Ep, Hp);
        scanC_kernel<<<(totA + 127)/128, 128>>>(dt, xc, xdbl, A_log, Dp, xz, Hp, y);
    }

    // 7. out_proj + residual (N=384,K=768): 128x64, 3 stages
    gemm_tf32<4,2,3><<<dim3((DM+63)/64, R/128), 256, SM_BIG>>>(
        y, DI, out_proj_w, x1, DM, DM, DI, nullptr, x, DM, 0);

    // 8. LN2
    ln_kernel<<<R, 128>>>(x1, ln2_w, ln2_b, u2);

    // 9. ffn1 + relu (N=1536,K=384): 128x64, 3 stages
    gemm_tf32<4,2,3><<<dim3((DFF+63)/64, R/128), 256, SM_BIG>>>(
        u2, DM, ffn_w1, hf, DFF, DFF, DM, ffn_b1, nullptr, 0, 2);

    // 10. ffn2 + bias + residual (N=384,K=1536): 128x64, 3 stages
    gemm_tf32<4,2,3><<<dim3((DM+63)/64, R/128), 256, SM_BIG>>>(
        hf, DFF, ffn_w2, out, DM, DM, DFF, ffn_b2, x1, DM, 0);
}